// round 1
// baseline (speedup 1.0000x reference)
#include <cuda_runtime.h>

// B3-spline undecimated wavelet transform (a trous), 3 levels.
// Input  x: (8, 1024, 1024) fp32
// Output  : (8, 4, 1024, 1024) fp32 = [w1, w2, w3, c3]
//
// Per level j (d = 2^j): c_j = sep5x5_b3(c_{j-1}, dilation d, reflect pad),
//                        w_j = c_{j-1} - c_j.
//
// One templated kernel per level; fused separable conv through shared memory.

#define IMG_N 1024
#define HW (IMG_N * IMG_N)
#define BATCH 8

// Scratch planes for c1, c2 (allocation-free rule: __device__ globals).
__device__ float g_scratch0[BATCH * HW];
__device__ float g_scratch1[BATCH * HW];

__device__ __forceinline__ int refl(int i, int n) {
    i = (i < 0) ? -i : i;
    return (i >= n) ? (2 * n - 2 - i) : i;
}

template <int D>
__global__ __launch_bounds__(256)
void uwt_level(const float* __restrict__ in, float* __restrict__ wout,
               float* __restrict__ cout,
               size_t in_bs, size_t w_bs, size_t c_bs)
{
    constexpr int TX = 64, TY = 64;
    constexpr int R  = 2 * D;                 // halo
    constexpr int RP = (R + 3) & ~3;          // halo padded to float4 boundary
    constexpr int RAWW = TX + 2 * RP;         // raw tile row stride (floats)
    constexpr int RAWH = TY + 2 * R;
    constexpr int LOADW = TX + 2 * R;         // actually-loaded width
    constexpr int NQ  = (R + RP + 7) / 4;     // float4 quads per H-window
    constexpr int OFS = RP - R;               // window start inside quads

    __shared__ __align__(16) float raw[RAWH * RAWW];
    __shared__ __align__(16) float hb[RAWH * TX];

    const int tid = threadIdx.x;
    const int bx = blockIdx.x, by = blockIdx.y, b = blockIdx.z;

    in   += (size_t)b * in_bs;
    wout += (size_t)b * w_bs;
    cout += (size_t)b * c_bs;

    const int N = IMG_N;

    // ---------- load tile + halo (reflect at image borders) ----------
    for (int idx = tid; idx < RAWH * LOADW; idx += 256) {
        int r = idx / LOADW;
        int j = idx - r * LOADW;
        int gy = refl(by * TY + r - R, N);
        int gx = refl(bx * TX + j - R, N);
        raw[r * RAWW + (j + OFS)] = __ldg(&in[(size_t)gy * N + gx]);
    }
    __syncthreads();

    constexpr float W0 = 1.0f / 16.0f;
    constexpr float W1 = 1.0f / 4.0f;
    constexpr float W2 = 3.0f / 8.0f;

    // ---------- horizontal pass: raw -> hb ----------
    // hb[r][c] = sum_k w[k] * raw[r][c + k*D + OFS]   (c in [0,TX))
    for (int q = tid; q < RAWH * (TX / 4); q += 256) {
        int r = q >> 4;            // TX/4 == 16
        int c = (q & 15) * 4;

        float v[NQ * 4];
        const float4* src = reinterpret_cast<const float4*>(&raw[r * RAWW + c]);
        #pragma unroll
        for (int i = 0; i < NQ; i++) {
            float4 t = src[i];
            v[4 * i + 0] = t.x; v[4 * i + 1] = t.y;
            v[4 * i + 2] = t.z; v[4 * i + 3] = t.w;
        }

        float4 o;
        o.x = W0 * (v[OFS + 0] + v[OFS + 0 + 4 * D]) + W1 * (v[OFS + 0 + D] + v[OFS + 0 + 3 * D]) + W2 * v[OFS + 0 + 2 * D];
        o.y = W0 * (v[OFS + 1] + v[OFS + 1 + 4 * D]) + W1 * (v[OFS + 1 + D] + v[OFS + 1 + 3 * D]) + W2 * v[OFS + 1 + 2 * D];
        o.z = W0 * (v[OFS + 2] + v[OFS + 2 + 4 * D]) + W1 * (v[OFS + 2 + D] + v[OFS + 2 + 3 * D]) + W2 * v[OFS + 2 + 2 * D];
        o.w = W0 * (v[OFS + 3] + v[OFS + 3 + 4 * D]) + W1 * (v[OFS + 3 + D] + v[OFS + 3 + 3 * D]) + W2 * v[OFS + 3 + 2 * D];

        *reinterpret_cast<float4*>(&hb[r * TX + c]) = o;
    }
    __syncthreads();

    // ---------- vertical pass + outputs ----------
    for (int q = tid; q < TY * (TX / 4); q += 256) {
        int y = q >> 4;
        int x = (q & 15) * 4;

        float4 a0 = *reinterpret_cast<const float4*>(&hb[(y        ) * TX + x]);
        float4 a1 = *reinterpret_cast<const float4*>(&hb[(y + 1 * D) * TX + x]);
        float4 a2 = *reinterpret_cast<const float4*>(&hb[(y + 2 * D) * TX + x]);
        float4 a3 = *reinterpret_cast<const float4*>(&hb[(y + 3 * D) * TX + x]);
        float4 a4 = *reinterpret_cast<const float4*>(&hb[(y + 4 * D) * TX + x]);
        float4 rv = *reinterpret_cast<const float4*>(&raw[(y + R) * RAWW + x + RP]);

        float4 cv, wv;
        cv.x = W0 * (a0.x + a4.x) + W1 * (a1.x + a3.x) + W2 * a2.x;
        cv.y = W0 * (a0.y + a4.y) + W1 * (a1.y + a3.y) + W2 * a2.y;
        cv.z = W0 * (a0.z + a4.z) + W1 * (a1.z + a3.z) + W2 * a2.z;
        cv.w = W0 * (a0.w + a4.w) + W1 * (a1.w + a3.w) + W2 * a2.w;
        wv.x = rv.x - cv.x;
        wv.y = rv.y - cv.y;
        wv.z = rv.z - cv.z;
        wv.w = rv.w - cv.w;

        size_t o = (size_t)(by * TY + y) * N + (size_t)bx * TX + x;
        *reinterpret_cast<float4*>(&cout[o]) = cv;
        *reinterpret_cast<float4*>(&wout[o]) = wv;
    }
}

extern "C" void kernel_launch(void* const* d_in, const int* in_sizes, int n_in,
                              void* d_out, int out_size)
{
    const float* x = (const float*)d_in[0];
    float* out = (float*)d_out;

    float *s0 = nullptr, *s1 = nullptr;
    cudaGetSymbolAddress((void**)&s0, g_scratch0);
    cudaGetSymbolAddress((void**)&s1, g_scratch1);

    dim3 grid(IMG_N / 64, IMG_N / 64, BATCH);
    dim3 blk(256);

    // Level 1 (d=1): in = x, w1 -> out ch0, c1 -> scratch0
    uwt_level<1><<<grid, blk>>>(x, out + 0 * (size_t)HW, s0,
                                (size_t)HW, (size_t)4 * HW, (size_t)HW);
    // Level 2 (d=2): in = c1, w2 -> out ch1, c2 -> scratch1
    uwt_level<2><<<grid, blk>>>(s0, out + 1 * (size_t)HW, s1,
                                (size_t)HW, (size_t)4 * HW, (size_t)HW);
    // Level 3 (d=4): in = c2, w3 -> out ch2, c3 -> out ch3
    uwt_level<4><<<grid, blk>>>(s1, out + 2 * (size_t)HW, out + 3 * (size_t)HW,
                                (size_t)HW, (size_t)4 * HW, (size_t)4 * HW);
}

// round 2
// speedup vs baseline: 1.1765x; 1.1765x over previous
#include <cuda_runtime.h>

// B3-spline undecimated wavelet transform (a trous), 3 levels.
// Input  x: (8, 1024, 1024) fp32 ; Output: (8, 4, 1024, 1024) = [w1,w2,w3,c3]
// Per level j (d=2^j): c_j = sep 5-tap B3 conv (reflect), w_j = c_{j-1} - c_j.

#define IMG_N 1024
#define HW (IMG_N * IMG_N)
#define BATCH 8

__device__ float g_scratch0[BATCH * HW];
__device__ float g_scratch1[BATCH * HW];

__device__ __forceinline__ int refl(int i, int n) {
    i = (i < 0) ? -i : i;
    return (i >= n) ? (2 * n - 2 - i) : i;
}

// SC = stream the c output too (final level: never re-read)
template <int D, bool SC>
__global__ __launch_bounds__(256)
void uwt_level(const float* __restrict__ in, float* __restrict__ wout,
               float* __restrict__ cout,
               size_t in_bs, size_t w_bs, size_t c_bs)
{
    constexpr int TX = 64, TY = 64;
    constexpr int R  = 2 * D;                 // halo
    constexpr int RP = (R + 3) & ~3;          // halo padded to float4 boundary
    constexpr int RAWW = TX + 2 * RP;         // raw tile row width (floats), mult of 4
    constexpr int RAWH = TY + 2 * R;
    constexpr int OFS  = RP - R;              // H-window start offset inside quads
    constexpr int NQR  = RAWW / 4;            // float4 per raw row
    constexpr int NQ   = (RP + R + 7) / 4;    // float4 quads needed per H window

    __shared__ __align__(16) float raw[RAWH * RAWW];
    __shared__ __align__(16) float hb[RAWH * TX];

    const int tid = threadIdx.x;
    const int bx = blockIdx.x, by = blockIdx.y, b = blockIdx.z;

    in   += (size_t)b * in_bs;
    wout += (size_t)b * w_bs;
    cout += (size_t)b * c_bs;

    const int N = IMG_N;
    const int gx0 = bx * TX - RP;             // 16B-aligned leftmost loaded col
    const bool colsafe = (gx0 >= 0) && (gx0 + RAWW <= N);

    // ---------- load tile + halo ----------
    if (colsafe) {
        // fully vectorized: columns in-bounds; rows reflected per-row (cheap)
        for (int idx = tid; idx < RAWH * NQR; idx += 256) {
            int r = idx / NQR;
            int q = idx - r * NQR;
            int gy = refl(by * TY + r - R, N);
            float4 t = __ldg(reinterpret_cast<const float4*>(
                             &in[(size_t)gy * N + gx0 + 4 * q]));
            *reinterpret_cast<float4*>(&raw[r * RAWW + 4 * q]) = t;
        }
    } else {
        // border blocks in x: scalar with full reflection
        for (int idx = tid; idx < RAWH * RAWW; idx += 256) {
            int r = idx / RAWW;
            int j = idx - r * RAWW;
            int gy = refl(by * TY + r - R, N);
            int gx = refl(gx0 + j, N);
            raw[r * RAWW + j] = __ldg(&in[(size_t)gy * N + gx]);
        }
    }
    __syncthreads();

    constexpr float W0 = 1.0f / 16.0f;
    constexpr float W1 = 1.0f / 4.0f;
    constexpr float W2 = 3.0f / 8.0f;

    // ---------- horizontal pass: raw -> hb ----------
    for (int q = tid; q < RAWH * (TX / 4); q += 256) {
        int r = q >> 4;               // TX/4 == 16
        int c = (q & 15) * 4;

        float v[NQ * 4];
        const float4* src = reinterpret_cast<const float4*>(&raw[r * RAWW + c]);
        #pragma unroll
        for (int i = 0; i < NQ; i++) {
            float4 t = src[i];
            v[4 * i + 0] = t.x; v[4 * i + 1] = t.y;
            v[4 * i + 2] = t.z; v[4 * i + 3] = t.w;
        }

        float4 o;
        o.x = W0 * (v[OFS + 0] + v[OFS + 0 + 4 * D]) + W1 * (v[OFS + 0 + D] + v[OFS + 0 + 3 * D]) + W2 * v[OFS + 0 + 2 * D];
        o.y = W0 * (v[OFS + 1] + v[OFS + 1 + 4 * D]) + W1 * (v[OFS + 1 + D] + v[OFS + 1 + 3 * D]) + W2 * v[OFS + 1 + 2 * D];
        o.z = W0 * (v[OFS + 2] + v[OFS + 2 + 4 * D]) + W1 * (v[OFS + 2 + D] + v[OFS + 2 + 3 * D]) + W2 * v[OFS + 2 + 2 * D];
        o.w = W0 * (v[OFS + 3] + v[OFS + 3 + 4 * D]) + W1 * (v[OFS + 3 + D] + v[OFS + 3 + 3 * D]) + W2 * v[OFS + 3 + 2 * D];

        *reinterpret_cast<float4*>(&hb[r * TX + c]) = o;
    }
    __syncthreads();

    // ---------- vertical pass + outputs ----------
    for (int q = tid; q < TY * (TX / 4); q += 256) {
        int y = q >> 4;
        int x = (q & 15) * 4;

        float4 a0 = *reinterpret_cast<const float4*>(&hb[(y        ) * TX + x]);
        float4 a1 = *reinterpret_cast<const float4*>(&hb[(y + 1 * D) * TX + x]);
        float4 a2 = *reinterpret_cast<const float4*>(&hb[(y + 2 * D) * TX + x]);
        float4 a3 = *reinterpret_cast<const float4*>(&hb[(y + 3 * D) * TX + x]);
        float4 a4 = *reinterpret_cast<const float4*>(&hb[(y + 4 * D) * TX + x]);
        float4 rv = *reinterpret_cast<const float4*>(&raw[(y + R) * RAWW + x + RP]);

        float4 cv, wv;
        cv.x = W0 * (a0.x + a4.x) + W1 * (a1.x + a3.x) + W2 * a2.x;
        cv.y = W0 * (a0.y + a4.y) + W1 * (a1.y + a3.y) + W2 * a2.y;
        cv.z = W0 * (a0.z + a4.z) + W1 * (a1.z + a3.z) + W2 * a2.z;
        cv.w = W0 * (a0.w + a4.w) + W1 * (a1.w + a3.w) + W2 * a2.w;
        wv.x = rv.x - cv.x;
        wv.y = rv.y - cv.y;
        wv.z = rv.z - cv.z;
        wv.w = rv.w - cv.w;

        size_t o = (size_t)(by * TY + y) * N + (size_t)bx * TX + x;
        // w planes are never re-read: stream past L2 so c-planes stay resident.
        __stcs(reinterpret_cast<float4*>(&wout[o]), wv);
        if (SC) {
            __stcs(reinterpret_cast<float4*>(&cout[o]), cv);
        } else {
            *reinterpret_cast<float4*>(&cout[o]) = cv;
        }
    }
}

extern "C" void kernel_launch(void* const* d_in, const int* in_sizes, int n_in,
                              void* d_out, int out_size)
{
    const float* x = (const float*)d_in[0];
    float* out = (float*)d_out;

    float *s0 = nullptr, *s1 = nullptr;
    cudaGetSymbolAddress((void**)&s0, g_scratch0);
    cudaGetSymbolAddress((void**)&s1, g_scratch1);

    dim3 grid(IMG_N / 64, IMG_N / 64, BATCH);
    dim3 blk(256);

    // Level 1 (d=1): in = x, w1 -> out ch0, c1 -> scratch0
    uwt_level<1, false><<<grid, blk>>>(x, out + 0 * (size_t)HW, s0,
                                       (size_t)HW, (size_t)4 * HW, (size_t)HW);
    // Level 2 (d=2): in = c1, w2 -> out ch1, c2 -> scratch1
    uwt_level<2, false><<<grid, blk>>>(s0, out + 1 * (size_t)HW, s1,
                                       (size_t)HW, (size_t)4 * HW, (size_t)HW);
    // Level 3 (d=4): in = c2, w3 -> out ch2, c3 -> out ch3
    uwt_level<4, true><<<grid, blk>>>(s1, out + 2 * (size_t)HW, out + 3 * (size_t)HW,
                                      (size_t)HW, (size_t)4 * HW, (size_t)4 * HW);
}

// round 4
// speedup vs baseline: 1.2318x; 1.0470x over previous
#include <cuda_runtime.h>

// B3-spline undecimated wavelet transform (a trous), 3 levels.
// Input  x: (8, 1024, 1024) fp32 ; Output: (8, 4, 1024, 1024) = [w1,w2,w3,c3]
// Per level j (d=2^j): c_j = sep 5-tap B3 conv (reflect), w_j = c_{j-1} - c_j.
//
// Levels 1,2 (D=1,2): register line-buffer kernel (no hb smem buffer, 1 barrier).
// Level 3 (D=4): two-phase smem kernel (register ring would need 17 f4 ring).

#define IMG_N 1024
#define HW (IMG_N * IMG_N)
#define BATCH 8

__device__ float g_scratch0[BATCH * HW];
__device__ float g_scratch1[BATCH * HW];

__device__ __forceinline__ int refl(int i, int n) {
    i = (i < 0) ? -i : i;
    return (i >= n) ? (2 * n - 2 - i) : i;
}

#define W0f (1.0f / 16.0f)
#define W1f (1.0f / 4.0f)
#define W2f (3.0f / 8.0f)

// Horizontal 5-tap conv at output quad (absolute smem col a0, 16B-aligned a0-4).
// v[j] = element (a0-4+j); taps for out lane i at v[i+4+k*D], k=-2..2. D<=2.
template <int D>
__device__ __forceinline__ float4 hconv(const float* rowp, int a0)
{
    float v[12];
    #pragma unroll
    for (int i = 0; i < 3; i++) {
        float4 t = *reinterpret_cast<const float4*>(rowp + a0 - 4 + 4 * i);
        v[4 * i + 0] = t.x; v[4 * i + 1] = t.y;
        v[4 * i + 2] = t.z; v[4 * i + 3] = t.w;
    }
    float4 o;
    o.x = W0f * (v[4 - 2 * D] + v[4 + 2 * D]) + W1f * (v[4 - D] + v[4 + D]) + W2f * v[4];
    o.y = W0f * (v[5 - 2 * D] + v[5 + 2 * D]) + W1f * (v[5 - D] + v[5 + D]) + W2f * v[5];
    o.z = W0f * (v[6 - 2 * D] + v[6 + 2 * D]) + W1f * (v[6 - D] + v[6 + D]) + W2f * v[6];
    o.w = W0f * (v[7 - 2 * D] + v[7 + 2 * D]) + W1f * (v[7 - D] + v[7 + D]) + W2f * v[7];
    return o;
}

// ---------------- register line-buffer kernel (D = 1 or 2) ----------------
template <int D>
__global__ __launch_bounds__(256, 3)
void uwt_reg(const float* __restrict__ in, float* __restrict__ wout,
             float* __restrict__ cout,
             size_t in_bs, size_t w_bs, size_t c_bs)
{
    constexpr int W = 128, TY = 64, S = 8;     // tile 128x64, 32 quads x 8 strips
    constexpr int R   = 2 * D;
    constexpr int RP  = (R + 3) & ~3;
    constexpr int STR = W + 2 * RP;            // smem row stride (floats)
    constexpr int ROWS = TY + 2 * R;
    constexpr int M = 4 * D + 1;               // H register ring size

    __shared__ __align__(16) float raw[ROWS * STR];

    const int tid = threadIdx.x;
    const int bx = blockIdx.x, by = blockIdx.y, b = blockIdx.z;

    in   += (size_t)b * in_bs;
    wout += (size_t)b * w_bs;
    cout += (size_t)b * c_bs;

    const int N = IMG_N;
    const int gx0 = bx * W - RP;               // 16B-aligned leftmost loaded col

    // ---- load tile + halo (vector fast path, scalar reflect on edge quads) ----
    for (int idx = tid; idx < ROWS * (STR / 4); idx += 256) {
        int r = idx / (STR / 4);
        int q = idx - r * (STR / 4);
        int gy = refl(by * TY + r - R, N);
        int gx = gx0 + 4 * q;
        const float* rowi = in + (size_t)gy * N;
        float4 t;
        if (gx >= 0 && gx + 4 <= N) {
            t = __ldg(reinterpret_cast<const float4*>(rowi + gx));
        } else {
            t.x = __ldg(rowi + refl(gx + 0, N));
            t.y = __ldg(rowi + refl(gx + 1, N));
            t.z = __ldg(rowi + refl(gx + 2, N));
            t.w = __ldg(rowi + refl(gx + 3, N));
        }
        *reinterpret_cast<float4*>(&raw[r * STR + 4 * q]) = t;
    }
    __syncthreads();

    // ---- H into register ring, V in registers, outputs straight to gmem ----
    const int quad  = tid & 31;                // 32 x-quads
    const int strip = tid >> 5;                // 8 y-strips of S=8 rows
    const int x  = quad * 4;
    const int y0 = strip * S;
    const int a0 = RP + x;

    float4 h[M];
    #pragma unroll
    for (int k = 0; k < 4 * D; k++)
        h[k] = hconv<D>(&raw[(y0 + k) * STR], a0);

    #pragma unroll
    for (int y = 0; y < S; y++) {
        h[(y + 4 * D) % M] = hconv<D>(&raw[(y0 + y + 4 * D) * STR], a0);

        float4 t0 = h[(y        ) % M];
        float4 t1 = h[(y + D    ) % M];
        float4 t2 = h[(y + 2 * D) % M];
        float4 t3 = h[(y + 3 * D) % M];
        float4 t4 = h[(y + 4 * D) % M];

        float4 cv;
        cv.x = W0f * (t0.x + t4.x) + W1f * (t1.x + t3.x) + W2f * t2.x;
        cv.y = W0f * (t0.y + t4.y) + W1f * (t1.y + t3.y) + W2f * t2.y;
        cv.z = W0f * (t0.z + t4.z) + W1f * (t1.z + t3.z) + W2f * t2.z;
        cv.w = W0f * (t0.w + t4.w) + W1f * (t1.w + t3.w) + W2f * t2.w;

        float4 rv = *reinterpret_cast<const float4*>(&raw[(y0 + y + R) * STR + a0]);
        float4 wv;
        wv.x = rv.x - cv.x; wv.y = rv.y - cv.y;
        wv.z = rv.z - cv.z; wv.w = rv.w - cv.w;

        size_t o = (size_t)(by * TY + y0 + y) * N + (size_t)bx * W + x;
        __stcs(reinterpret_cast<float4*>(&wout[o]), wv);   // never re-read
        *reinterpret_cast<float4*>(&cout[o]) = cv;         // re-read next level
    }
}

// ---------------- two-phase smem kernel (D = 4, final level) ----------------
template <int D, bool SC>
__global__ __launch_bounds__(256)
void uwt_level(const float* __restrict__ in, float* __restrict__ wout,
               float* __restrict__ cout,
               size_t in_bs, size_t w_bs, size_t c_bs)
{
    constexpr int TX = 64, TY = 64;
    constexpr int R  = 2 * D;
    constexpr int RP = (R + 3) & ~3;
    constexpr int RAWW = TX + 2 * RP;
    constexpr int RAWH = TY + 2 * R;
    constexpr int OFS  = RP - R;
    constexpr int NQR  = RAWW / 4;
    constexpr int NQ   = (RP + R + 7) / 4;

    __shared__ __align__(16) float raw[RAWH * RAWW];
    __shared__ __align__(16) float hb[RAWH * TX];

    const int tid = threadIdx.x;
    const int bx = blockIdx.x, by = blockIdx.y, b = blockIdx.z;

    in   += (size_t)b * in_bs;
    wout += (size_t)b * w_bs;
    cout += (size_t)b * c_bs;

    const int N = IMG_N;
    const int gx0 = bx * TX - RP;
    const bool colsafe = (gx0 >= 0) && (gx0 + RAWW <= N);

    if (colsafe) {
        for (int idx = tid; idx < RAWH * NQR; idx += 256) {
            int r = idx / NQR;
            int q = idx - r * NQR;
            int gy = refl(by * TY + r - R, N);
            float4 t = __ldg(reinterpret_cast<const float4*>(
                             &in[(size_t)gy * N + gx0 + 4 * q]));
            *reinterpret_cast<float4*>(&raw[r * RAWW + 4 * q]) = t;
        }
    } else {
        for (int idx = tid; idx < RAWH * RAWW; idx += 256) {
            int r = idx / RAWW;
            int j = idx - r * RAWW;
            int gy = refl(by * TY + r - R, N);
            int gx = refl(gx0 + j, N);
            raw[r * RAWW + j] = __ldg(&in[(size_t)gy * N + gx]);
        }
    }
    __syncthreads();

    for (int q = tid; q < RAWH * (TX / 4); q += 256) {
        int r = q >> 4;
        int c = (q & 15) * 4;

        float v[NQ * 4];
        const float4* src = reinterpret_cast<const float4*>(&raw[r * RAWW + c]);
        #pragma unroll
        for (int i = 0; i < NQ; i++) {
            float4 t = src[i];
            v[4 * i + 0] = t.x; v[4 * i + 1] = t.y;
            v[4 * i + 2] = t.z; v[4 * i + 3] = t.w;
        }

        float4 o;
        o.x = W0f * (v[OFS + 0] + v[OFS + 0 + 4 * D]) + W1f * (v[OFS + 0 + D] + v[OFS + 0 + 3 * D]) + W2f * v[OFS + 0 + 2 * D];
        o.y = W0f * (v[OFS + 1] + v[OFS + 1 + 4 * D]) + W1f * (v[OFS + 1 + D] + v[OFS + 1 + 3 * D]) + W2f * v[OFS + 1 + 2 * D];
        o.z = W0f * (v[OFS + 2] + v[OFS + 2 + 4 * D]) + W1f * (v[OFS + 2 + D] + v[OFS + 2 + 3 * D]) + W2f * v[OFS + 2 + 2 * D];
        o.w = W0f * (v[OFS + 3] + v[OFS + 3 + 4 * D]) + W1f * (v[OFS + 3 + D] + v[OFS + 3 + 3 * D]) + W2f * v[OFS + 3 + 2 * D];

        *reinterpret_cast<float4*>(&hb[r * TX + c]) = o;
    }
    __syncthreads();

    for (int q = tid; q < TY * (TX / 4); q += 256) {
        int y = q >> 4;
        int x = (q & 15) * 4;

        float4 a0 = *reinterpret_cast<const float4*>(&hb[(y        ) * TX + x]);
        float4 a1 = *reinterpret_cast<const float4*>(&hb[(y + 1 * D) * TX + x]);
        float4 a2 = *reinterpret_cast<const float4*>(&hb[(y + 2 * D) * TX + x]);
        float4 a3 = *reinterpret_cast<const float4*>(&hb[(y + 3 * D) * TX + x]);
        float4 a4 = *reinterpret_cast<const float4*>(&hb[(y + 4 * D) * TX + x]);
        float4 rv = *reinterpret_cast<const float4*>(&raw[(y + R) * RAWW + x + RP]);

        float4 cv, wv;
        cv.x = W0f * (a0.x + a4.x) + W1f * (a1.x + a3.x) + W2f * a2.x;
        cv.y = W0f * (a0.y + a4.y) + W1f * (a1.y + a3.y) + W2f * a2.y;
        cv.z = W0f * (a0.z + a4.z) + W1f * (a1.z + a3.z) + W2f * a2.z;
        cv.w = W0f * (a0.w + a4.w) + W1f * (a1.w + a3.w) + W2f * a2.w;
        wv.x = rv.x - cv.x;
        wv.y = rv.y - cv.y;
        wv.z = rv.z - cv.z;
        wv.w = rv.w - cv.w;

        size_t o = (size_t)(by * TY + y) * N + (size_t)bx * TX + x;
        __stcs(reinterpret_cast<float4*>(&wout[o]), wv);
        if (SC) {
            __stcs(reinterpret_cast<float4*>(&cout[o]), cv);
        } else {
            *reinterpret_cast<float4*>(&cout[o]) = cv;
        }
    }
}

extern "C" void kernel_launch(void* const* d_in, const int* in_sizes, int n_in,
                              void* d_out, int out_size)
{
    const float* x = (const float*)d_in[0];
    float* out = (float*)d_out;

    float *s0 = nullptr, *s1 = nullptr;
    cudaGetSymbolAddress((void**)&s0, g_scratch0);
    cudaGetSymbolAddress((void**)&s1, g_scratch1);

    dim3 gridReg(IMG_N / 128, IMG_N / 64, BATCH);   // 8 x 16 x 8
    dim3 gridHb(IMG_N / 64, IMG_N / 64, BATCH);     // 16 x 16 x 8
    dim3 blk(256);

    // Level 1 (d=1): in = x, w1 -> out ch0, c1 -> scratch0
    uwt_reg<1><<<gridReg, blk>>>(x, out + 0 * (size_t)HW, s0,
                                 (size_t)HW, (size_t)4 * HW, (size_t)HW);
    // Level 2 (d=2): in = c1, w2 -> out ch1, c2 -> scratch1
    uwt_reg<2><<<gridReg, blk>>>(s0, out + 1 * (size_t)HW, s1,
                                 (size_t)HW, (size_t)4 * HW, (size_t)HW);
    // Level 3 (d=4): in = c2, w3 -> out ch2, c3 -> out ch3
    uwt_level<4, true><<<gridHb, blk>>>(s1, out + 2 * (size_t)HW, out + 3 * (size_t)HW,
                                        (size_t)HW, (size_t)4 * HW, (size_t)4 * HW);
}

// round 5
// speedup vs baseline: 1.2708x; 1.0316x over previous
#include <cuda_runtime.h>

// B3-spline undecimated wavelet transform (a trous), 3 levels — FULLY FUSED.
// Input  x: (8, 1024, 1024) fp32 ; Output: (8, 4, 1024, 1024) = [w1,w2,w3,c3]
//
// One kernel: each block owns a 64x64 output tile, loads it + 16/14 halo
// (reflect at image borders — reflection commutes with the symmetric filter),
// then runs H/V passes for d=1,2,4 through two smem buffers. V-passes write
// c_j in-place into A (per-element, same thread reads then writes), so
// w_j = c_{j-1} - c_j needs no extra buffer. All outputs streamed (__stcs).

#define IMG_N 1024
#define HW (IMG_N * IMG_N)
#define BATCH 8

#define TS   64      // output tile
#define HA   16      // col pad: logical cols [-16, 80)
#define ROW0 14      // row pad: logical rows [-14, 78)
#define ROWS 92
#define STR  96      // smem row stride (floats), == loaded col count
#define NTHR 512

#define W0f (1.0f / 16.0f)
#define W1f (1.0f / 4.0f)
#define W2f (3.0f / 8.0f)

#define SMEM_BYTES (2 * ROWS * STR * 4)

__device__ __forceinline__ int refl(int i, int n) {
    i = (i < 0) ? -i : i;
    return (i >= n) ? (2 * n - 2 - i) : i;
}

// Horizontal 5-tap at one float4 quad. p points at lane-0's smem element
// (16B aligned). Reads NQ aligned quads around it.
template <int D>
__device__ __forceinline__ float4 hconv(const float* p)
{
    constexpr int VO = (D <= 2) ? 4 : 8;   // aligned left extension
    constexpr int NQ = (D <= 2) ? 3 : 5;
    float v[NQ * 4];
    #pragma unroll
    for (int i = 0; i < NQ; i++) {
        float4 t = *reinterpret_cast<const float4*>(p - VO + 4 * i);
        v[4 * i + 0] = t.x; v[4 * i + 1] = t.y;
        v[4 * i + 2] = t.z; v[4 * i + 3] = t.w;
    }
    float4 o;
    o.x = W0f * (v[0 + VO - 2 * D] + v[0 + VO + 2 * D]) + W1f * (v[0 + VO - D] + v[0 + VO + D]) + W2f * v[0 + VO];
    o.y = W0f * (v[1 + VO - 2 * D] + v[1 + VO + 2 * D]) + W1f * (v[1 + VO - D] + v[1 + VO + D]) + W2f * v[1 + VO];
    o.z = W0f * (v[2 + VO - 2 * D] + v[2 + VO + 2 * D]) + W1f * (v[2 + VO - D] + v[2 + VO + D]) + W2f * v[2 + VO];
    o.w = W0f * (v[3 + VO - 2 * D] + v[3 + VO + 2 * D]) + W1f * (v[3 + VO - D] + v[3 + VO + D]) + W2f * v[3 + VO];
    return o;
}

__device__ __forceinline__ float4 vcomb(float4 a0, float4 a1, float4 a2,
                                        float4 a3, float4 a4)
{
    float4 c;
    c.x = W0f * (a0.x + a4.x) + W1f * (a1.x + a3.x) + W2f * a2.x;
    c.y = W0f * (a0.y + a4.y) + W1f * (a1.y + a3.y) + W2f * a2.y;
    c.z = W0f * (a0.z + a4.z) + W1f * (a1.z + a3.z) + W2f * a2.z;
    c.w = W0f * (a0.w + a4.w) + W1f * (a1.w + a3.w) + W2f * a2.w;
    return c;
}

__global__ void __launch_bounds__(NTHR, 2)
uwt_fused(const float* __restrict__ x, float* __restrict__ out)
{
    extern __shared__ __align__(16) float smem[];
    float* A = smem;                    // current c_{j-1} (in-place updated)
    float* B = smem + ROWS * STR;       // H-pass scratch

    const int tid = threadIdx.x;
    const int bx = blockIdx.x, by = blockIdx.y, b = blockIdx.z;

    const float* in = x + (size_t)b * HW;
    float* w1p = out + ((size_t)b * 4 + 0) * HW;
    float* w2p = out + ((size_t)b * 4 + 1) * HW;
    float* w3p = out + ((size_t)b * 4 + 2) * HW;
    float* c3p = out + ((size_t)b * 4 + 3) * HW;

    const int gx0 = bx * TS - HA;       // logical col -16 (16B aligned in gmem)
    const int gy0 = by * TS;

    // ---------------- load x tile + halo ----------------
    const bool colsafe = (gx0 >= 0) && (gx0 + STR <= IMG_N);
    if (colsafe) {
        for (int i = tid; i < ROWS * (STR / 4); i += NTHR) {
            int r = i / (STR / 4);
            int q = i - r * (STR / 4);
            int gy = refl(gy0 + r - ROW0, IMG_N);
            float4 t = __ldg(reinterpret_cast<const float4*>(
                             in + (size_t)gy * IMG_N + gx0 + 4 * q));
            *reinterpret_cast<float4*>(&A[r * STR + 4 * q]) = t;
        }
    } else {
        for (int i = tid; i < ROWS * STR; i += NTHR) {
            int r = i / STR;
            int c = i - r * STR;
            int gy = refl(gy0 + r - ROW0, IMG_N);
            int gx = refl(gx0 + c, IMG_N);
            A[r * STR + c] = __ldg(in + (size_t)gy * IMG_N + gx);
        }
    }
    __syncthreads();

    // per-level geometry (logical coords):
    //  L1 (D=1): H rows [-14,78) 92, quads start -12, 22;  V rows [-12,76) 88
    //  L2 (D=2): H rows [-12,76) 88, quads start  -8, 20;  V rows  [-8,72) 80
    //  L3 (D=4): H rows  [-8,72) 80, quads start   0, 16;  V rows   [0,64) 64

    // =============== level macro bodies ===============
    // ---- level 1 ----
    {
        constexpr int D = 1, NRH = 92, RH0 = -14, QN = 22, LC0 = -12, NRV = 88, RV0 = -12;
        for (int i = tid; i < NRH * QN; i += NTHR) {
            int rr = i / QN, qq = i - rr * QN;
            int idx = (RH0 + rr + ROW0) * STR + (LC0 + 4 * qq + HA);
            *reinterpret_cast<float4*>(&B[idx]) = hconv<D>(&A[idx]);
        }
        __syncthreads();
        for (int i = tid; i < NRV * QN; i += NTHR) {
            int rr = i / QN, qq = i - rr * QN;
            int y = RV0 + rr, col = LC0 + 4 * qq;
            int idx = (y + ROW0) * STR + (col + HA);
            float4 t0 = *reinterpret_cast<const float4*>(&B[idx - 2 * D * STR]);
            float4 t1 = *reinterpret_cast<const float4*>(&B[idx - 1 * D * STR]);
            float4 t2 = *reinterpret_cast<const float4*>(&B[idx]);
            float4 t3 = *reinterpret_cast<const float4*>(&B[idx + 1 * D * STR]);
            float4 t4 = *reinterpret_cast<const float4*>(&B[idx + 2 * D * STR]);
            float4 cv = vcomb(t0, t1, t2, t3, t4);
            float4 pv = *reinterpret_cast<const float4*>(&A[idx]);
            *reinterpret_cast<float4*>(&A[idx]) = cv;
            if ((unsigned)y < (unsigned)TS && (unsigned)col < (unsigned)TS) {
                float4 wv;
                wv.x = pv.x - cv.x; wv.y = pv.y - cv.y;
                wv.z = pv.z - cv.z; wv.w = pv.w - cv.w;
                size_t o = (size_t)(gy0 + y) * IMG_N + bx * TS + col;
                __stcs(reinterpret_cast<float4*>(&w1p[o]), wv);
            }
        }
        __syncthreads();
    }
    // ---- level 2 ----
    {
        constexpr int D = 2, NRH = 88, RH0 = -12, QN = 20, LC0 = -8, NRV = 80, RV0 = -8;
        for (int i = tid; i < NRH * QN; i += NTHR) {
            int rr = i / QN, qq = i - rr * QN;
            int idx = (RH0 + rr + ROW0) * STR + (LC0 + 4 * qq + HA);
            *reinterpret_cast<float4*>(&B[idx]) = hconv<D>(&A[idx]);
        }
        __syncthreads();
        for (int i = tid; i < NRV * QN; i += NTHR) {
            int rr = i / QN, qq = i - rr * QN;
            int y = RV0 + rr, col = LC0 + 4 * qq;
            int idx = (y + ROW0) * STR + (col + HA);
            float4 t0 = *reinterpret_cast<const float4*>(&B[idx - 2 * D * STR]);
            float4 t1 = *reinterpret_cast<const float4*>(&B[idx - 1 * D * STR]);
            float4 t2 = *reinterpret_cast<const float4*>(&B[idx]);
            float4 t3 = *reinterpret_cast<const float4*>(&B[idx + 1 * D * STR]);
            float4 t4 = *reinterpret_cast<const float4*>(&B[idx + 2 * D * STR]);
            float4 cv = vcomb(t0, t1, t2, t3, t4);
            float4 pv = *reinterpret_cast<const float4*>(&A[idx]);
            *reinterpret_cast<float4*>(&A[idx]) = cv;
            if ((unsigned)y < (unsigned)TS && (unsigned)col < (unsigned)TS) {
                float4 wv;
                wv.x = pv.x - cv.x; wv.y = pv.y - cv.y;
                wv.z = pv.z - cv.z; wv.w = pv.w - cv.w;
                size_t o = (size_t)(gy0 + y) * IMG_N + bx * TS + col;
                __stcs(reinterpret_cast<float4*>(&w2p[o]), wv);
            }
        }
        __syncthreads();
    }
    // ---- level 3 (outputs only) ----
    {
        constexpr int D = 4, NRH = 80, RH0 = -8, QN = 16, LC0 = 0, NRV = 64, RV0 = 0;
        for (int i = tid; i < NRH * QN; i += NTHR) {
            int rr = i / QN, qq = i - rr * QN;
            int idx = (RH0 + rr + ROW0) * STR + (LC0 + 4 * qq + HA);
            *reinterpret_cast<float4*>(&B[idx]) = hconv<D>(&A[idx]);
        }
        __syncthreads();
        for (int i = tid; i < NRV * QN; i += NTHR) {
            int rr = i >> 4, qq = i & 15;          // QN = 16
            int y = RV0 + rr, col = LC0 + 4 * qq;
            int idx = (y + ROW0) * STR + (col + HA);
            float4 t0 = *reinterpret_cast<const float4*>(&B[idx - 2 * D * STR]);
            float4 t1 = *reinterpret_cast<const float4*>(&B[idx - 1 * D * STR]);
            float4 t2 = *reinterpret_cast<const float4*>(&B[idx]);
            float4 t3 = *reinterpret_cast<const float4*>(&B[idx + 1 * D * STR]);
            float4 t4 = *reinterpret_cast<const float4*>(&B[idx + 2 * D * STR]);
            float4 cv = vcomb(t0, t1, t2, t3, t4);
            float4 pv = *reinterpret_cast<const float4*>(&A[idx]);
            float4 wv;
            wv.x = pv.x - cv.x; wv.y = pv.y - cv.y;
            wv.z = pv.z - cv.z; wv.w = pv.w - cv.w;
            size_t o = (size_t)(gy0 + y) * IMG_N + bx * TS + col;
            __stcs(reinterpret_cast<float4*>(&w3p[o]), wv);
            __stcs(reinterpret_cast<float4*>(&c3p[o]), cv);
        }
    }
}

extern "C" void kernel_launch(void* const* d_in, const int* in_sizes, int n_in,
                              void* d_out, int out_size)
{
    const float* x = (const float*)d_in[0];
    float* out = (float*)d_out;

    static bool attr_set = false;
    if (!attr_set) {
        cudaFuncSetAttribute(uwt_fused,
                             cudaFuncAttributeMaxDynamicSharedMemorySize,
                             SMEM_BYTES);
        attr_set = true;
    }

    dim3 grid(IMG_N / TS, IMG_N / TS, BATCH);   // 16 x 16 x 8
    uwt_fused<<<grid, NTHR, SMEM_BYTES>>>(x, out);
}

// round 7
// speedup vs baseline: 1.6027x; 1.2612x over previous
#include <cuda_runtime.h>

// B3-spline UWT (a trous), 3 levels, FULLY FUSED, register-ring H+V.
// Input x: (8,1024,1024) fp32 ; Output: (8,4,1024,1024) = [w1,w2,w3,c3]
//
// Per 64x64 tile: load tile + 16/14 reflect halo into smem A.
// Level j: each thread owns one x-quad and one dilation-residue row chunk;
// computes horizontal conv rows on the fly from the c_{j-1} buffer (3-5
// LDS.128 each) into a 5-deep register ring, does the vertical conv in
// registers (dilation-residue decomposition => ring is always 5), writes
// c_j to the other smem buffer, streams w_j to gmem. One barrier per level.

#define IMG_N 1024
#define HW (IMG_N * IMG_N)
#define BATCH 8

#define TS   64
#define HA   16      // col pad: logical cols [-16, 80)
#define ROW0 14      // row pad: logical rows [-14, 78)
#define ROWS 92
#define STR  96
#define NTHR 256
#define SMEM_BYTES (2 * ROWS * STR * 4)

#define W0f (1.0f / 16.0f)
#define W1f (1.0f / 4.0f)
#define W2f (3.0f / 8.0f)

__device__ __forceinline__ int refl(int i, int n) {
    i = (i < 0) ? -i : i;
    return (i >= n) ? (2 * n - 2 - i) : i;
}

// Horizontal 5-tap conv at one quad; p = smem ptr to lane-0 element (16B
// aligned). Also returns the center quad (pv = c_{j-1} at this location).
template <int D>
__device__ __forceinline__ float4 hconv_pv(const float* p, float4& pv)
{
    constexpr int VO = (D <= 2) ? 4 : 8;
    constexpr int NQ = (D <= 2) ? 3 : 5;
    float v[NQ * 4];
    #pragma unroll
    for (int i = 0; i < NQ; i++) {
        float4 t = *reinterpret_cast<const float4*>(p - VO + 4 * i);
        v[4 * i + 0] = t.x; v[4 * i + 1] = t.y;
        v[4 * i + 2] = t.z; v[4 * i + 3] = t.w;
    }
    pv.x = v[VO + 0]; pv.y = v[VO + 1]; pv.z = v[VO + 2]; pv.w = v[VO + 3];
    float4 o;
    o.x = W0f * (v[VO + 0 - 2 * D] + v[VO + 0 + 2 * D]) + W1f * (v[VO + 0 - D] + v[VO + 0 + D]) + W2f * v[VO + 0];
    o.y = W0f * (v[VO + 1 - 2 * D] + v[VO + 1 + 2 * D]) + W1f * (v[VO + 1 - D] + v[VO + 1 + D]) + W2f * v[VO + 1];
    o.z = W0f * (v[VO + 2 - 2 * D] + v[VO + 2 + 2 * D]) + W1f * (v[VO + 2 - D] + v[VO + 2 + D]) + W2f * v[VO + 2];
    o.w = W0f * (v[VO + 3 - 2 * D] + v[VO + 3 + 2 * D]) + W1f * (v[VO + 3 - D] + v[VO + 3 + D]) + W2f * v[VO + 3];
    return o;
}

// One wavelet level.
//  S: smem buffer with c_{j-1};  Dst: smem buffer for c_j (unused if LAST).
//  Work item = (x-quad, row class). Row class = (residue mod D, chunk of M
//  sub-rows). Output rows y = y0 + t*D, t in [0,M). V-conv taps in the
//  sub-sampled grid are stride-1 => 5-deep H ring.
template <int D, int M, int QN, int LC0, int RC, int RV0, bool LAST>
__device__ __forceinline__ void do_level(const float* __restrict__ S,
                                         float* __restrict__ Dst,
                                         float* __restrict__ wpl,
                                         float* __restrict__ cpl,
                                         int gy0, int gxb)
{
    const int item = threadIdx.x;
    if (item < QN * RC) {
        const int quad  = item % QN;
        const int cls   = item / QN;
        const int res   = (D == 1) ? 0 : (cls % D);
        const int chunk = (D == 1) ? cls : (cls / D);
        const int col   = LC0 + 4 * quad;
        const int y0    = RV0 + res + chunk * (M * D);
        const float* base = S + ROW0 * STR + HA + col;

        float4 h[5], pv[3];
        #pragma unroll
        for (int u = 0; u < 4; u++) {
            float4 pp;
            h[u % 5] = hconv_pv<D>(base + (y0 + (u - 2) * D) * STR, pp);
            pv[u % 3] = pp;
        }
        #pragma unroll
        for (int t = 0; t < M; t++) {
            const int u = t + 4;
            float4 pp;
            h[u % 5] = hconv_pv<D>(base + (y0 + (u - 2) * D) * STR, pp);
            pv[u % 3] = pp;

            float4 a0 = h[(t + 0) % 5], a1 = h[(t + 1) % 5], a2 = h[(t + 2) % 5];
            float4 a3 = h[(t + 3) % 5], a4 = h[(t + 4) % 5];
            float4 cv;
            cv.x = W0f * (a0.x + a4.x) + W1f * (a1.x + a3.x) + W2f * a2.x;
            cv.y = W0f * (a0.y + a4.y) + W1f * (a1.y + a3.y) + W2f * a2.y;
            cv.z = W0f * (a0.z + a4.z) + W1f * (a1.z + a3.z) + W2f * a2.z;
            cv.w = W0f * (a0.w + a4.w) + W1f * (a1.w + a3.w) + W2f * a2.w;

            const float4 p = pv[(t + 2) % 3];
            const int y = y0 + t * D;

            if (!LAST)
                *reinterpret_cast<float4*>(Dst + (y + ROW0) * STR + HA + col) = cv;

            float4 wv;
            wv.x = p.x - cv.x; wv.y = p.y - cv.y;
            wv.z = p.z - cv.z; wv.w = p.w - cv.w;

            if (LAST) {
                size_t o = (size_t)(gy0 + y) * IMG_N + gxb + col;
                __stcs(reinterpret_cast<float4*>(&wpl[o]), wv);
                __stcs(reinterpret_cast<float4*>(&cpl[o]), cv);
            } else if ((unsigned)y < (unsigned)TS && (unsigned)col < (unsigned)TS) {
                size_t o = (size_t)(gy0 + y) * IMG_N + gxb + col;
                __stcs(reinterpret_cast<float4*>(&wpl[o]), wv);
            }
        }
    }
    if (!LAST) __syncthreads();
}

__global__ void __launch_bounds__(NTHR, 3)
uwt_fused(const float* __restrict__ x, float* __restrict__ out)
{
    extern __shared__ __align__(16) float smem[];
    float* A = smem;                    // c0, then c2
    float* B = smem + ROWS * STR;       // c1

    const int tid = threadIdx.x;
    const int bx = blockIdx.x, by = blockIdx.y, b = blockIdx.z;

    const float* in = x + (size_t)b * HW;
    float* w1p = out + ((size_t)b * 4 + 0) * HW;
    float* w2p = out + ((size_t)b * 4 + 1) * HW;
    float* w3p = out + ((size_t)b * 4 + 2) * HW;
    float* c3p = out + ((size_t)b * 4 + 3) * HW;

    const int gx0 = bx * TS - HA;
    const int gy0 = by * TS;
    const int gxb = bx * TS;

    // ---------------- load x tile + halo into A ----------------
    const bool colsafe = (gx0 >= 0) && (gx0 + STR <= IMG_N);
    if (colsafe) {
        for (int i = tid; i < ROWS * (STR / 4); i += NTHR) {
            int r = i / (STR / 4);
            int q = i - r * (STR / 4);
            int gy = refl(gy0 + r - ROW0, IMG_N);
            float4 t = __ldg(reinterpret_cast<const float4*>(
                             in + (size_t)gy * IMG_N + gx0 + 4 * q));
            *reinterpret_cast<float4*>(&A[r * STR + 4 * q]) = t;
        }
    } else {
        for (int i = tid; i < ROWS * STR; i += NTHR) {
            int r = i / STR;
            int c = i - r * STR;
            int gy = refl(gy0 + r - ROW0, IMG_N);
            int gx = refl(gx0 + c, IMG_N);
            A[r * STR + c] = __ldg(in + (size_t)gy * IMG_N + gx);
        }
    }
    __syncthreads();

    // L1 (D=1): c1 over rows/cols [-12,76);  22 quads x 11 chunks of 8 rows
    do_level<1, 8, 22, -12, 11, -12, false>(A, B, w1p, nullptr, gy0, gxb);
    // L2 (D=2): c2 over rows/cols [-8,72);   20 quads x (2 res x 5 chunks)
    do_level<2, 8, 20, -8, 10, -8, false>(B, A, w2p, nullptr, gy0, gxb);
    // L3 (D=4): outputs only, rows/cols [0,64); 16 quads x (4 res x 4 chunks of 4)
    do_level<4, 4, 16, 0, 16, 0, true>(A, nullptr, w3p, c3p, gy0, gxb);
}

extern "C" void kernel_launch(void* const* d_in, const int* in_sizes, int n_in,
                              void* d_out, int out_size)
{
    const float* x = (const float*)d_in[0];
    float* out = (float*)d_out;

    static bool attr_set = false;
    if (!attr_set) {
        cudaFuncSetAttribute(uwt_fused,
                             cudaFuncAttributeMaxDynamicSharedMemorySize,
                             SMEM_BYTES);
        attr_set = true;
    }

    dim3 grid(IMG_N / TS, IMG_N / TS, BATCH);   // 16 x 16 x 8
    uwt_fused<<<grid, NTHR, SMEM_BYTES>>>(x, out);
}